// round 16
// baseline (speedup 1.0000x reference)
#include <cuda_runtime.h>
#include <cuda_fp16.h>
#include <cstdint>

#define MM 10000
static __device__ unsigned short g_adj_h[(size_t)MM * MM];   // adj as fp16 (200MB)
static __device__ unsigned short g_x_h[(size_t)MM * 1024];
static __device__ unsigned short g_w1t[512 * 1024];
static __device__ unsigned short g_w2t[256 * 512];
static __device__ unsigned short g_w3t[128 * 256];
static __device__ unsigned short g_Ht[(size_t)512 * MM];     // transposed feature outputs
static __device__ unsigned short g_X[(size_t)MM * 512];      // row-major intermediates
static __device__ float g_P[(size_t)8 * MM * 512];           // split-K fp32 partials (164MB)
static __device__ unsigned g_mask[MM * 512 / 32];            // dropout bitmask

// X2 stored scaled by 1/64 in fp16 (column-mean amplification through adj
// reaches ~2e5, over fp16 max); final combine un-scales by 64. Exact (pow2).
#define X2_INV_SCALE 0.015625f
#define X2_SCALE 64.0f

// ------------------------------ helpers -----------------------------------
__device__ __forceinline__ uint32_t smem_u32(const void* p) {
    uint32_t a;
    asm("{ .reg .u64 t; cvta.to.shared.u64 t, %1; cvt.u32.u64 %0, t; }" : "=r"(a) : "l"(p));
    return a;
}
__device__ __forceinline__ void cp_async16(uint32_t dst, const void* src, uint32_t sz) {
    asm volatile("cp.async.cg.shared.global [%0], [%1], 16, %2;" :: "r"(dst), "l"(src), "r"(sz) : "memory");
}
__device__ __forceinline__ void cp_commit() { asm volatile("cp.async.commit_group;" ::: "memory"); }
template <int N> __device__ __forceinline__ void cp_wait() {
    asm volatile("cp.async.wait_group %0;" :: "n"(N) : "memory");
}
__device__ __forceinline__ void ldsm4(uint32_t& r0, uint32_t& r1, uint32_t& r2, uint32_t& r3,
                                      uint32_t addr) {
    asm volatile("ldmatrix.sync.aligned.m8n8.x4.shared.b16 {%0,%1,%2,%3}, [%4];"
                 : "=r"(r0), "=r"(r1), "=r"(r2), "=r"(r3) : "r"(addr));
}
__device__ __forceinline__ void mma16(float* c, const uint32_t* a, const uint32_t* b) {
    asm volatile(
        "mma.sync.aligned.m16n8k16.row.col.f32.f16.f16.f32 "
        "{%0,%1,%2,%3}, {%4,%5,%6,%7}, {%8,%9}, {%0,%1,%2,%3};"
        : "+f"(c[0]), "+f"(c[1]), "+f"(c[2]), "+f"(c[3])
        : "r"(a[0]), "r"(a[1]), "r"(a[2]), "r"(a[3]), "r"(b[0]), "r"(b[1]));
}

// ----------------------- dropout mask (JAX threefry) -----------------------
__device__ __forceinline__ unsigned rotl32(unsigned v, int s) { return (v << s) | (v >> (32 - s)); }
__device__ __forceinline__ bool dropout_keep(unsigned idx) {
    const unsigned ks1 = 42u, ks2 = 0x1BD11BDAu ^ 42u;
    unsigned x0 = 0u, x1 = idx + ks1;
#define TF_R(r) { x0 += x1; x1 = rotl32(x1, (r)); x1 ^= x0; }
    TF_R(13) TF_R(15) TF_R(26) TF_R(6)  x0 += ks1; x1 += ks2 + 1u;
    TF_R(17) TF_R(29) TF_R(16) TF_R(24) x0 += ks2; x1 += 2u;
    TF_R(13) TF_R(15) TF_R(26) TF_R(6)  x0 += 0u;  x1 += ks1 + 3u;
    TF_R(17) TF_R(29) TF_R(16) TF_R(24) x0 += ks1; x1 += ks2 + 4u;
    TF_R(13) TF_R(15) TF_R(26) TF_R(6)  x0 += ks2; x1 += 5u;
#undef TF_R
    return ((x0 ^ x1) & 0x80000000u) == 0u;
}
__global__ void mask_k(int total) {
    int i = blockIdx.x * blockDim.x + threadIdx.x;
    bool k = (i < total) && dropout_keep((unsigned)i);
    unsigned b = __ballot_sync(0xFFFFFFFF, k);
    if ((threadIdx.x & 31) == 0 && i < total) g_mask[i >> 5] = b;
}

// ------------------------------ prep kernels -------------------------------
__global__ void tohalf2_k(const float* __restrict__ inA, __half2* __restrict__ outA, int n4A,
                          const float* __restrict__ inB, __half2* __restrict__ outB, int n4B) {
    int i = blockIdx.x * blockDim.x + threadIdx.x, st = gridDim.x * blockDim.x;
    for (; i < n4A + n4B; i += st) {
        const float4* in = (i < n4A) ? (const float4*)inA : (const float4*)inB;
        __half2* out = (i < n4A) ? outA : outB;
        int j = (i < n4A) ? i : i - n4A;
        float4 v = in[j];
        out[2 * j]     = __floats2half2_rn(v.x, v.y);
        out[2 * j + 1] = __floats2half2_rn(v.z, v.w);
    }
}
// W [K,N] fp32 row-major -> Wt [N,K] fp16 row-major
__global__ void transpose_k(const float* __restrict__ in, __half* __restrict__ out, int K, int N) {
    __shared__ float t[32][33];
    int n0 = blockIdx.x * 32, k0 = blockIdx.y * 32;
    for (int i = 0; i < 32; i += 8) {
        int k = k0 + threadIdx.y + i, n = n0 + threadIdx.x;
        if (k < K && n < N) t[threadIdx.y + i][threadIdx.x] = in[(size_t)k * N + n];
    }
    __syncthreads();
    for (int i = 0; i < 32; i += 8) {
        int n = n0 + threadIdx.y + i, k = k0 + threadIdx.x;
        if (n < N && k < K) out[(size_t)n * K + k] = __float2half_rn(t[threadIdx.x][threadIdx.y + i]);
    }
}

// ------------------------------ fp16 MMA GEMM ------------------------------
// C = A[M,Kstride] @ Bt[N,Kstride]^T over K range [z*kLen, min((z+1)*kLen, K)).
// kLen MUST be a multiple of 8 halves so z*kLen is 16B-aligned (cp.async).
// Templated tile: BN=256 -> 512 thr, STG=4, 1 CTA/SM (RF-capped anyway).
//                 BN=128 -> 256 thr, STG=3, 2 CTAs/SM.
// Warp grid 2 x (BN/32), warp tile 64x32. Single-barrier multistage.
// Next-chunk cp.async is issued in 4 parts interleaved with the ks loop so
// LDGSTS issue overlaps HMMA issue instead of bursting after the barrier.
// TRANS: store C^T as fp16 (raw accumulator). Else: fp32 partial to slab z.
constexpr int BM = 128, BK = 64;

template <int BN> struct GCfg {
    static constexpr int THREADS = BN * 2;
    static constexpr int STG = (BN == 256) ? 4 : 3;
    static constexpr int MINCTA = (BN == 256) ? 1 : 2;
    static constexpr int ASZ = BM * 128;
    static constexpr int BSZ = BN * 128;
    static constexpr int SSZ = ASZ + BSZ;
    static constexpr int SMEM = SSZ * STG + 1024;
};

template <int BN, bool TRANS>
__global__ void __launch_bounds__(GCfg<BN>::THREADS, GCfg<BN>::MINCTA)
gemm_h(const __half* __restrict__ A, const __half* __restrict__ Bt,
       void* __restrict__ Cv, int M, int N, int Kstride, int kLen) {
    constexpr int THREADS = GCfg<BN>::THREADS, STG = GCfg<BN>::STG;
    constexpr int ASZ = GCfg<BN>::ASZ, SSZ = GCfg<BN>::SSZ;
    extern __shared__ char smraw[];
    const uint32_t base = (smem_u32(smraw) + 1023) & ~1023u;

    const int tid = threadIdx.x, lane = tid & 31, wid = tid >> 5;
    const int warpM = wid & 1, warpN = wid >> 1;           // 2 x BN/32 warp grid
    const int m0 = blockIdx.y * BM, n0 = blockIdx.x * BN;
    const int kOff = blockIdx.z * kLen;
    int kl = Kstride - kOff;                 // clamp last split
    if (kl > kLen) kl = kLen;
    const int nc = (kl + BK - 1) / BK;

    float acc[4][4][4];
#pragma unroll
    for (int a = 0; a < 4; a++)
#pragma unroll
        for (int b = 0; b < 4; b++)
#pragma unroll
            for (int i = 0; i < 4; i++) acc[a][b][i] = 0.0f;

    const uint32_t q = lane & 7;
    const uint32_t hA = lane >> 4;
    const uint32_t hB = (lane >> 3) & 1;
    const uint32_t aF = base + (uint32_t)(warpM * 64 + (lane & 15)) * 128;
    const uint32_t bF = base + ASZ + (uint32_t)(warpN * 32 + ((lane >> 4) << 3) + (lane & 7)) * 128;

    const __half* Abase = A + kOff;
    const __half* Bbase = Bt + kOff;

    // loads one quarter (groups 2p, 2p+1) of chunk c into stage s
    auto load_part = [&](int c, int s, int p) {
        const int k0 = c * BK, kRem = kl - k0;
        const uint32_t sb = base + (uint32_t)s * SSZ;
#pragma unroll
        for (int i = tid; i < BM * 2; i += THREADS) {
            const int row = i >> 1, g = 2 * p + (i & 1);
            const bool v = (m0 + row) < M && g * 8 < kRem;
            cp_async16(sb + (uint32_t)(row * 128) + (uint32_t)((g ^ (row & 7)) << 4),
                       Abase + (size_t)(m0 + row) * Kstride + k0 + g * 8, v ? 16u : 0u);
        }
#pragma unroll
        for (int i = tid; i < BN * 2; i += THREADS) {
            const int row = i >> 1, g = 2 * p + (i & 1);
            const bool v = g * 8 < kRem;
            cp_async16(sb + (uint32_t)ASZ + (uint32_t)(row * 128) + (uint32_t)((g ^ (row & 7)) << 4),
                       Bbase + (size_t)(n0 + row) * Kstride + k0 + g * 8, v ? 16u : 0u);
        }
    };

    for (int s = 0; s < STG - 1; s++) {
        if (s < nc)
#pragma unroll
            for (int p = 0; p < 4; p++) load_part(s, s, p);
        cp_commit();
    }

    for (int c = 0; c < nc; c++) {
        cp_wait<STG - 2>();
        __syncthreads();
        const bool pf = (c + STG - 1 < nc);
        const int pc = c + STG - 1, ps = pc % STG;
        const uint32_t sb = (uint32_t)(c % STG) * SSZ;
#pragma unroll
        for (int ks = 0; ks < 4; ks++) {
            if (pf) load_part(pc, ps, ks);   // interleave next-chunk loads
            uint32_t afr[4][4], bfr[4][2];
#pragma unroll
            for (int mt = 0; mt < 4; mt++)
                ldsm4(afr[mt][0], afr[mt][1], afr[mt][2], afr[mt][3],
                      aF + sb + (uint32_t)(mt * 2048) + ((((uint32_t)ks * 2 + hA) ^ q) << 4));
#pragma unroll
            for (int np = 0; np < 2; np++) {
                uint32_t r0, r1, r2, r3;
                ldsm4(r0, r1, r2, r3,
                      bF + sb + (uint32_t)(np * 2048) + ((((uint32_t)ks * 2 + hB) ^ q) << 4));
                bfr[np * 2][0] = r0;     bfr[np * 2][1] = r1;
                bfr[np * 2 + 1][0] = r2; bfr[np * 2 + 1][1] = r3;
            }
#pragma unroll
            for (int mt = 0; mt < 4; mt++)
#pragma unroll
                for (int nt = 0; nt < 4; nt++)
                    mma16(acc[mt][nt], afr[mt], bfr[nt]);
        }
        cp_commit();
    }

    // ---------------- epilogue ----------------
    const int rBase = m0 + warpM * 64 + (lane >> 2);
    const int cBase = n0 + warpN * 32 + (lane & 3) * 2;
#pragma unroll
    for (int mt = 0; mt < 4; mt++) {
#pragma unroll
        for (int hf = 0; hf < 2; hf++) {
            const int r = rBase + mt * 16 + hf * 8;
            if (r < M) {
#pragma unroll
                for (int nt = 0; nt < 4; nt++) {
                    const int cc = cBase + nt * 8;
                    const float v0 = acc[mt][nt][hf * 2 + 0];
                    const float v1 = acc[mt][nt][hf * 2 + 1];
                    if (TRANS) {
                        __half* C = (__half*)Cv;
                        C[(size_t)cc * M + r] = __float2half_rn(v0);
                        C[(size_t)(cc + 1) * M + r] = __float2half_rn(v1);
                    } else {
                        float* C = (float*)Cv + (size_t)blockIdx.z * M * N;
                        *(float2*)&C[(size_t)r * N + cc] = make_float2(v0, v1);
                    }
                }
            }
        }
    }
}

// --------------------- split-K combine + layer epilogue --------------------
// Sums nslab fp32 partial slabs, then:
// MODE 1: bias,relu,dropout -> half | MODE 2: bias, /64 -> half | MODE 3: *64, bias -> fp32
template <int MODE>
__global__ void combine_k(const float* __restrict__ P, const float* __restrict__ bias,
                          void* __restrict__ out, int Mn, int N, int nslab) {
    int i = blockIdx.x * blockDim.x + threadIdx.x;
    if (i >= Mn) return;
    float v = P[i];
    for (int s = 1; s < nslab; s++) v += P[(size_t)s * Mn + i];
    if (MODE == 1) {
        v += bias[i % N];
        v = fmaxf(v, 0.0f);
        v = ((g_mask[i >> 5] >> (i & 31)) & 1u) ? v * 2.0f : 0.0f;
        ((__half*)out)[i] = __float2half_rn(v);
    } else if (MODE == 2) {
        v += bias[i % N];
        ((__half*)out)[i] = __float2half_rn(v * X2_INV_SCALE);
    } else {
        v = v * X2_SCALE + bias[i % N];
        ((float*)out)[i] = v;
    }
}

// ------------------------------ launch -------------------------------------
extern "C" void kernel_launch(void* const* d_in, const int* in_sizes, int n_in,
                              void* d_out, int out_size) {
    const float* x   = (const float*)d_in[0];
    const float* adj = (const float*)d_in[1];
    const float* W1  = (const float*)d_in[2];
    const float* b1  = (const float*)d_in[3];
    const float* W2  = (const float*)d_in[4];
    const float* b2  = (const float*)d_in[5];
    const float* W3  = (const float*)d_in[6];
    const float* b3  = (const float*)d_in[7];
    float* out = (float*)d_out;

    __half *adjH, *xH, *w1t, *w2t, *w3t, *Ht, *X;
    float* P;
    cudaGetSymbolAddress((void**)&adjH, g_adj_h);
    cudaGetSymbolAddress((void**)&xH, g_x_h);
    cudaGetSymbolAddress((void**)&w1t, g_w1t);
    cudaGetSymbolAddress((void**)&w2t, g_w2t);
    cudaGetSymbolAddress((void**)&w3t, g_w3t);
    cudaGetSymbolAddress((void**)&Ht, g_Ht);
    cudaGetSymbolAddress((void**)&X, g_X);
    cudaGetSymbolAddress((void**)&P, g_P);

    const int M = MM, MT = (M + BM - 1) / BM;  // 79
    cudaFuncSetAttribute(gemm_h<256, true>,  cudaFuncAttributeMaxDynamicSharedMemorySize, GCfg<256>::SMEM);
    cudaFuncSetAttribute(gemm_h<256, false>, cudaFuncAttributeMaxDynamicSharedMemorySize, GCfg<256>::SMEM);
    cudaFuncSetAttribute(gemm_h<128, true>,  cudaFuncAttributeMaxDynamicSharedMemorySize, GCfg<128>::SMEM);
    cudaFuncSetAttribute(gemm_h<128, false>, cudaFuncAttributeMaxDynamicSharedMemorySize, GCfg<128>::SMEM);

    // BN=256: 1 CTA/SM, 148 slots/wave. L1b z=8 (kLen=1256) / L2b z=16 (kLen=632)
    // -> 1264-CTA grids = 8.54 waves (94.6%). L3 uses BN=128 variant (2 CTA/SM).
    // kLen multiples of 8 halves (16B-aligned). ncu idx 3 = L1b adj GEMM.
    tohalf2_k<<<4096, 256>>>(adj, (__half2*)adjH, M * (M / 4),
                             x, (__half2*)xH, M * 256);                       // 0
    transpose_k<<<dim3(16, 32), dim3(32, 8)>>>(W1, w1t, 1024, 512);           // 1
    // L1: H1t = (x@W1)^T ; P = adj@H1 (split-K=8) ; X1 = drop(relu(P+b1))
    gemm_h<256, true><<<dim3(2, MT, 1), 512, GCfg<256>::SMEM>>>(xH, w1t, Ht, M, 512, 1024, 1024);  // 2
    gemm_h<256, false><<<dim3(2, MT, 8), 512, GCfg<256>::SMEM>>>(adjH, Ht, P, M, 512, M, 1256);    // 3 <- ncu
    mask_k<<<(M * 512) / 256, 256>>>(M * 512);                                // 4
    combine_k<1><<<(M * 512 + 255) / 256, 256>>>(P, b1, X, M * 512, 512, 8);  // 5
    // L2: H2t = (X1@W2)^T ; X2 = (adj@H2 + b2)/64, split-K=16 (kLen=632)
    transpose_k<<<dim3(8, 16), dim3(32, 8)>>>(W2, w2t, 512, 256);             // 6
    gemm_h<256, true><<<dim3(1, MT, 1), 512, GCfg<256>::SMEM>>>(X, w2t, Ht, M, 256, 512, 512);     // 7
    gemm_h<256, false><<<dim3(1, MT, 16), 512, GCfg<256>::SMEM>>>(adjH, Ht, P, M, 256, M, 632);    // 8
    combine_k<2><<<(M * 256 + 255) / 256, 256>>>(P, b2, X, M * 256, 256, 16); // 9
    // L3: H3t = ((X2/64)@W3)^T ; out = 64*(adj@H3) + b3, split-K=16 (kLen=632)
    transpose_k<<<dim3(4, 8), dim3(32, 8)>>>(W3, w3t, 256, 128);              // 10
    gemm_h<128, true><<<dim3(1, MT, 1), 256, GCfg<128>::SMEM>>>(X, w3t, Ht, M, 128, 256, 256);     // 11
    gemm_h<128, false><<<dim3(1, MT, 16), 256, GCfg<128>::SMEM>>>(adjH, Ht, P, M, 128, M, 632);    // 12
    combine_k<3><<<(M * 128 + 255) / 256, 256>>>(P, b3, out, M * 128, 128, 16); // 13
}

// round 17
// speedup vs baseline: 1.0889x; 1.0889x over previous
#include <cuda_runtime.h>
#include <cuda_fp16.h>
#include <cstdint>

#define MM 10000
static __device__ unsigned short g_adj_h[(size_t)MM * MM];   // adj as fp16 (200MB)
static __device__ unsigned short g_x_h[(size_t)MM * 1024];
static __device__ unsigned short g_w1t[512 * 1024];
static __device__ unsigned short g_w2t[256 * 512];
static __device__ unsigned short g_w3t[128 * 256];
static __device__ unsigned short g_Ht[(size_t)512 * MM];     // transposed feature outputs
static __device__ unsigned short g_X[(size_t)MM * 512];      // row-major intermediates
static __device__ float g_P[(size_t)8 * MM * 512];           // split-K fp32 partials (164MB)
static __device__ unsigned g_mask[MM * 512 / 32];            // dropout bitmask

// X2 stored scaled by 1/64 in fp16 (column-mean amplification through adj
// reaches ~2e5, over fp16 max); final combine un-scales by 64. Exact (pow2).
#define X2_INV_SCALE 0.015625f
#define X2_SCALE 64.0f

// ------------------------------ helpers -----------------------------------
__device__ __forceinline__ uint32_t smem_u32(const void* p) {
    uint32_t a;
    asm("{ .reg .u64 t; cvta.to.shared.u64 t, %1; cvt.u32.u64 %0, t; }" : "=r"(a) : "l"(p));
    return a;
}
__device__ __forceinline__ void cp_async16(uint32_t dst, const void* src, uint32_t sz) {
    asm volatile("cp.async.cg.shared.global [%0], [%1], 16, %2;" :: "r"(dst), "l"(src), "r"(sz) : "memory");
}
__device__ __forceinline__ void cp_commit() { asm volatile("cp.async.commit_group;" ::: "memory"); }
template <int N> __device__ __forceinline__ void cp_wait() {
    asm volatile("cp.async.wait_group %0;" :: "n"(N) : "memory");
}
__device__ __forceinline__ void ldsm4(uint32_t& r0, uint32_t& r1, uint32_t& r2, uint32_t& r3,
                                      uint32_t addr) {
    asm volatile("ldmatrix.sync.aligned.m8n8.x4.shared.b16 {%0,%1,%2,%3}, [%4];"
                 : "=r"(r0), "=r"(r1), "=r"(r2), "=r"(r3) : "r"(addr));
}
__device__ __forceinline__ void mma16(float* c, const uint32_t* a, const uint32_t* b) {
    asm volatile(
        "mma.sync.aligned.m16n8k16.row.col.f32.f16.f16.f32 "
        "{%0,%1,%2,%3}, {%4,%5,%6,%7}, {%8,%9}, {%0,%1,%2,%3};"
        : "+f"(c[0]), "+f"(c[1]), "+f"(c[2]), "+f"(c[3])
        : "r"(a[0]), "r"(a[1]), "r"(a[2]), "r"(a[3]), "r"(b[0]), "r"(b[1]));
}

// ----------------------- dropout mask (JAX threefry) -----------------------
__device__ __forceinline__ unsigned rotl32(unsigned v, int s) { return (v << s) | (v >> (32 - s)); }
__device__ __forceinline__ bool dropout_keep(unsigned idx) {
    const unsigned ks1 = 42u, ks2 = 0x1BD11BDAu ^ 42u;
    unsigned x0 = 0u, x1 = idx + ks1;
#define TF_R(r) { x0 += x1; x1 = rotl32(x1, (r)); x1 ^= x0; }
    TF_R(13) TF_R(15) TF_R(26) TF_R(6)  x0 += ks1; x1 += ks2 + 1u;
    TF_R(17) TF_R(29) TF_R(16) TF_R(24) x0 += ks2; x1 += 2u;
    TF_R(13) TF_R(15) TF_R(26) TF_R(6)  x0 += 0u;  x1 += ks1 + 3u;
    TF_R(17) TF_R(29) TF_R(16) TF_R(24) x0 += ks1; x1 += ks2 + 4u;
    TF_R(13) TF_R(15) TF_R(26) TF_R(6)  x0 += ks2; x1 += 5u;
#undef TF_R
    return ((x0 ^ x1) & 0x80000000u) == 0u;
}
__global__ void mask_k(int total) {
    int i = blockIdx.x * blockDim.x + threadIdx.x;
    bool k = (i < total) && dropout_keep((unsigned)i);
    unsigned b = __ballot_sync(0xFFFFFFFF, k);
    if ((threadIdx.x & 31) == 0 && i < total) g_mask[i >> 5] = b;
}

// ------------------------------ prep kernels -------------------------------
__global__ void tohalf_k(const float* __restrict__ in, __half2* __restrict__ out, int n4) {
    int i = blockIdx.x * blockDim.x + threadIdx.x, st = gridDim.x * blockDim.x;
    for (; i < n4; i += st) {
        float4 v = ((const float4*)in)[i];
        out[2 * i]     = __floats2half2_rn(v.x, v.y);
        out[2 * i + 1] = __floats2half2_rn(v.z, v.w);
    }
}
// W [K,N] fp32 row-major -> Wt [N,K] fp16 row-major
__global__ void transpose_k(const float* __restrict__ in, __half* __restrict__ out, int K, int N) {
    __shared__ float t[32][33];
    int n0 = blockIdx.x * 32, k0 = blockIdx.y * 32;
    for (int i = 0; i < 32; i += 8) {
        int k = k0 + threadIdx.y + i, n = n0 + threadIdx.x;
        if (k < K && n < N) t[threadIdx.y + i][threadIdx.x] = in[(size_t)k * N + n];
    }
    __syncthreads();
    for (int i = 0; i < 32; i += 8) {
        int n = n0 + threadIdx.y + i, k = k0 + threadIdx.x;
        if (n < N && k < K) out[(size_t)n * K + k] = __float2half_rn(t[threadIdx.x][threadIdx.y + i]);
    }
}

// ------------------------------ fp16 MMA GEMM ------------------------------
// C = A[M,Kstride] @ Bt[N,Kstride]^T over K range [z*kLen, min((z+1)*kLen, K)).
// kLen MUST be a multiple of 8 halves so z*kLen is 16B-aligned (cp.async).
// Templated tile: BN=256 -> 512 thr, STG=4, 1 CTA/SM (RF-capped anyway).
//                 BN=128 -> 256 thr, STG=3, 2 CTAs/SM.
// Warp grid 2 x (BN/32), warp tile 64x32. Single-barrier multistage.
// TRANS: store C^T as fp16 (raw accumulator). Else: fp32 partial to slab z.
constexpr int BM = 128, BK = 64;

template <int BN> struct GCfg {
    static constexpr int THREADS = BN * 2;
    static constexpr int STG = (BN == 256) ? 4 : 3;
    static constexpr int MINCTA = (BN == 256) ? 1 : 2;
    static constexpr int ASZ = BM * 128;
    static constexpr int BSZ = BN * 128;
    static constexpr int SSZ = ASZ + BSZ;
    static constexpr int SMEM = SSZ * STG + 1024;
};

template <int BN, bool TRANS>
__global__ void __launch_bounds__(GCfg<BN>::THREADS, GCfg<BN>::MINCTA)
gemm_h(const __half* __restrict__ A, const __half* __restrict__ Bt,
       void* __restrict__ Cv, int M, int N, int Kstride, int kLen) {
    constexpr int THREADS = GCfg<BN>::THREADS, STG = GCfg<BN>::STG;
    constexpr int ASZ = GCfg<BN>::ASZ, SSZ = GCfg<BN>::SSZ;
    extern __shared__ char smraw[];
    const uint32_t base = (smem_u32(smraw) + 1023) & ~1023u;

    const int tid = threadIdx.x, lane = tid & 31, wid = tid >> 5;
    const int warpM = wid & 1, warpN = wid >> 1;           // 2 x BN/32 warp grid
    const int m0 = blockIdx.y * BM, n0 = blockIdx.x * BN;
    const int kOff = blockIdx.z * kLen;
    int kl = Kstride - kOff;                 // clamp last split
    if (kl > kLen) kl = kLen;
    const int nc = (kl + BK - 1) / BK;

    float acc[4][4][4];
#pragma unroll
    for (int a = 0; a < 4; a++)
#pragma unroll
        for (int b = 0; b < 4; b++)
#pragma unroll
            for (int i = 0; i < 4; i++) acc[a][b][i] = 0.0f;

    const uint32_t q = lane & 7;
    const uint32_t hA = lane >> 4;
    const uint32_t hB = (lane >> 3) & 1;
    const uint32_t aF = base + (uint32_t)(warpM * 64 + (lane & 15)) * 128;
    const uint32_t bF = base + ASZ + (uint32_t)(warpN * 32 + ((lane >> 4) << 3) + (lane & 7)) * 128;

    const __half* Abase = A + kOff;
    const __half* Bbase = Bt + kOff;

    auto load_chunk = [&](int c, int s) {
        const int k0 = c * BK, kRem = kl - k0;
        const uint32_t sb = base + (uint32_t)s * SSZ;
#pragma unroll
        for (int i = tid; i < BM * 8; i += THREADS) {
            const int row = i >> 3, g = i & 7;
            const bool v = (m0 + row) < M && g * 8 < kRem;
            cp_async16(sb + (uint32_t)(row * 128) + (uint32_t)((g ^ (row & 7)) << 4),
                       Abase + (size_t)(m0 + row) * Kstride + k0 + g * 8, v ? 16u : 0u);
        }
#pragma unroll
        for (int i = tid; i < BN * 8; i += THREADS) {
            const int row = i >> 3, g = i & 7;
            const bool v = g * 8 < kRem;
            cp_async16(sb + (uint32_t)ASZ + (uint32_t)(row * 128) + (uint32_t)((g ^ (row & 7)) << 4),
                       Bbase + (size_t)(n0 + row) * Kstride + k0 + g * 8, v ? 16u : 0u);
        }
    };

    for (int s = 0; s < STG - 1; s++) {
        if (s < nc) load_chunk(s, s);
        cp_commit();
    }

    for (int c = 0; c < nc; c++) {
        cp_wait<STG - 2>();
        __syncthreads();
        if (c + STG - 1 < nc) load_chunk(c + STG - 1, (c + STG - 1) % STG);
        cp_commit();
        const uint32_t sb = (uint32_t)(c % STG) * SSZ;
#pragma unroll
        for (int ks = 0; ks < 4; ks++) {
            uint32_t afr[4][4], bfr[4][2];
#pragma unroll
            for (int mt = 0; mt < 4; mt++)
                ldsm4(afr[mt][0], afr[mt][1], afr[mt][2], afr[mt][3],
                      aF + sb + (uint32_t)(mt * 2048) + ((((uint32_t)ks * 2 + hA) ^ q) << 4));
#pragma unroll
            for (int np = 0; np < 2; np++) {
                uint32_t r0, r1, r2, r3;
                ldsm4(r0, r1, r2, r3,
                      bF + sb + (uint32_t)(np * 2048) + ((((uint32_t)ks * 2 + hB) ^ q) << 4));
                bfr[np * 2][0] = r0;     bfr[np * 2][1] = r1;
                bfr[np * 2 + 1][0] = r2; bfr[np * 2 + 1][1] = r3;
            }
#pragma unroll
            for (int mt = 0; mt < 4; mt++)
#pragma unroll
                for (int nt = 0; nt < 4; nt++)
                    mma16(acc[mt][nt], afr[mt], bfr[nt]);
        }
    }

    // ---------------- epilogue ----------------
    const int rBase = m0 + warpM * 64 + (lane >> 2);
    const int cBase = n0 + warpN * 32 + (lane & 3) * 2;
#pragma unroll
    for (int mt = 0; mt < 4; mt++) {
#pragma unroll
        for (int hf = 0; hf < 2; hf++) {
            const int r = rBase + mt * 16 + hf * 8;
            if (r < M) {
#pragma unroll
                for (int nt = 0; nt < 4; nt++) {
                    const int cc = cBase + nt * 8;
                    const float v0 = acc[mt][nt][hf * 2 + 0];
                    const float v1 = acc[mt][nt][hf * 2 + 1];
                    if (TRANS) {
                        __half* C = (__half*)Cv;
                        C[(size_t)cc * M + r] = __float2half_rn(v0);
                        C[(size_t)(cc + 1) * M + r] = __float2half_rn(v1);
                    } else {
                        float* C = (float*)Cv + (size_t)blockIdx.z * M * N;
                        *(float2*)&C[(size_t)r * N + cc] = make_float2(v0, v1);
                    }
                }
            }
        }
    }
}

// --------------------- split-K combine + layer epilogue --------------------
// Vectorized: 4 consecutive elements per thread (Mn % 4 == 0, N % 4 == 0).
// MODE 1: bias,relu,dropout -> half | MODE 2: bias, /64 -> half | MODE 3: *64, bias -> fp32
template <int MODE>
__global__ void combine_k(const float* __restrict__ P, const float* __restrict__ bias,
                          void* __restrict__ out, int Mn, int N, int nslab) {
    int i = (blockIdx.x * blockDim.x + threadIdx.x) * 4;
    if (i >= Mn) return;
    float4 v = *(const float4*)&P[i];
    for (int s = 1; s < nslab; s++) {
        float4 p = *(const float4*)&P[(size_t)s * Mn + i];
        v.x += p.x; v.y += p.y; v.z += p.z; v.w += p.w;
    }
    const float4 b = *(const float4*)&bias[i % N];
    float r[4];
    if (MODE == 3) {
        r[0] = v.x * X2_SCALE + b.x; r[1] = v.y * X2_SCALE + b.y;
        r[2] = v.z * X2_SCALE + b.z; r[3] = v.w * X2_SCALE + b.w;
        *(float4*)((float*)out + i) = make_float4(r[0], r[1], r[2], r[3]);
        return;
    }
    r[0] = v.x + b.x; r[1] = v.y + b.y; r[2] = v.z + b.z; r[3] = v.w + b.w;
    if (MODE == 1) {
        const unsigned mw = g_mask[i >> 5] >> (i & 31);
#pragma unroll
        for (int j = 0; j < 4; j++) {
            r[j] = fmaxf(r[j], 0.0f);
            r[j] = ((mw >> j) & 1u) ? r[j] * 2.0f : 0.0f;
        }
    } else {
#pragma unroll
        for (int j = 0; j < 4; j++) r[j] *= X2_INV_SCALE;
    }
    __half2* o = (__half2*)((__half*)out + i);
    o[0] = __floats2half2_rn(r[0], r[1]);
    o[1] = __floats2half2_rn(r[2], r[3]);
}

// ------------------------------ launch -------------------------------------
extern "C" void kernel_launch(void* const* d_in, const int* in_sizes, int n_in,
                              void* d_out, int out_size) {
    const float* x   = (const float*)d_in[0];
    const float* adj = (const float*)d_in[1];
    const float* W1  = (const float*)d_in[2];
    const float* b1  = (const float*)d_in[3];
    const float* W2  = (const float*)d_in[4];
    const float* b2  = (const float*)d_in[5];
    const float* W3  = (const float*)d_in[6];
    const float* b3  = (const float*)d_in[7];
    float* out = (float*)d_out;

    __half *adjH, *xH, *w1t, *w2t, *w3t, *Ht, *X;
    float* P;
    cudaGetSymbolAddress((void**)&adjH, g_adj_h);
    cudaGetSymbolAddress((void**)&xH, g_x_h);
    cudaGetSymbolAddress((void**)&w1t, g_w1t);
    cudaGetSymbolAddress((void**)&w2t, g_w2t);
    cudaGetSymbolAddress((void**)&w3t, g_w3t);
    cudaGetSymbolAddress((void**)&Ht, g_Ht);
    cudaGetSymbolAddress((void**)&X, g_X);
    cudaGetSymbolAddress((void**)&P, g_P);

    const int M = MM, MT = (M + BM - 1) / BM;  // 79
    cudaFuncSetAttribute(gemm_h<256, true>,  cudaFuncAttributeMaxDynamicSharedMemorySize, GCfg<256>::SMEM);
    cudaFuncSetAttribute(gemm_h<256, false>, cudaFuncAttributeMaxDynamicSharedMemorySize, GCfg<256>::SMEM);
    cudaFuncSetAttribute(gemm_h<128, true>,  cudaFuncAttributeMaxDynamicSharedMemorySize, GCfg<128>::SMEM);
    cudaFuncSetAttribute(gemm_h<128, false>, cudaFuncAttributeMaxDynamicSharedMemorySize, GCfg<128>::SMEM);

    // Side stream: convert adj (DRAM-bound, ~90us) concurrently with the
    // default-stream L1 front (x convert, W1 transpose, L1a GEMM, mask).
    // Standard capture-fork: event on default -> s2 waits -> work -> event ->
    // default waits before L1b (first consumer of adjH).
    cudaStream_t s2;
    cudaStreamCreate(&s2);
    cudaEvent_t evFork, evAdj;
    cudaEventCreateWithFlags(&evFork, cudaEventDisableTiming);
    cudaEventCreateWithFlags(&evAdj, cudaEventDisableTiming);

    cudaEventRecord(evFork, 0);
    cudaStreamWaitEvent(s2, evFork, 0);
    tohalf_k<<<4096, 256, 0, s2>>>(adj, (__half2*)adjH, M * (M / 4));
    cudaEventRecord(evAdj, s2);

    // default stream: L1 front (overlaps with adj conversion)
    tohalf_k<<<1024, 256>>>(x, (__half2*)xH, M * 256);
    transpose_k<<<dim3(16, 32), dim3(32, 8)>>>(W1, w1t, 1024, 512);
    gemm_h<256, true><<<dim3(2, MT, 1), 512, GCfg<256>::SMEM>>>(xH, w1t, Ht, M, 512, 1024, 1024);
    mask_k<<<(M * 512) / 256, 256>>>(M * 512);
    transpose_k<<<dim3(8, 16), dim3(32, 8)>>>(W2, w2t, 512, 256);
    transpose_k<<<dim3(4, 8), dim3(32, 8)>>>(W3, w3t, 256, 128);

    cudaStreamWaitEvent(0, evAdj, 0);   // join: adjH ready

    // L1b: P = adj@H1 (split-K=8, kLen=1256) ; X1 = drop(relu(P+b1))
    gemm_h<256, false><<<dim3(2, MT, 8), 512, GCfg<256>::SMEM>>>(adjH, Ht, P, M, 512, M, 1256);
    combine_k<1><<<(M * 512 / 4 + 255) / 256, 256>>>(P, b1, X, M * 512, 512, 8);
    // L2: H2t = (X1@W2)^T ; X2 = (adj@H2 + b2)/64, split-K=16 (kLen=632)
    gemm_h<256, true><<<dim3(1, MT, 1), 512, GCfg<256>::SMEM>>>(X, w2t, Ht, M, 256, 512, 512);
    gemm_h<256, false><<<dim3(1, MT, 16), 512, GCfg<256>::SMEM>>>(adjH, Ht, P, M, 256, M, 632);
    combine_k<2><<<(M * 256 / 4 + 255) / 256, 256>>>(P, b2, X, M * 256, 256, 16);
    // L3: H3t = ((X2/64)@W3)^T ; out = 64*(adj@H3) + b3, split-K=16 (kLen=632)
    gemm_h<128, true><<<dim3(1, MT, 1), 256, GCfg<128>::SMEM>>>(X, w3t, Ht, M, 128, 256, 256);
    gemm_h<128, false><<<dim3(1, MT, 16), 256, GCfg<128>::SMEM>>>(adjH, Ht, P, M, 128, M, 632);
    combine_k<3><<<(M * 128 / 4 + 255) / 256, 256>>>(P, b3, out, M * 128, 128, 16);
}